// round 17
// baseline (speedup 1.0000x reference)
#include <cuda_runtime.h>
#include <cuda_fp16.h>
#include <stdint.h>

typedef __half f16;

#define S_LEN 512
#define BATCH 128
#define IDIM  1024
#define HDIM  1024
#define KDIM  2048       // packed Whh at k offset IDIM in g_W
#define N3    3072       // 3 gates * H, interleaved col = 3*j + gate
#define MTOT  (S_LEN*BATCH)

#define TN_S  48               // per-CTA N tile
#define NBLK_S (N3/TN_S)       // 64

// ---- persistent kernel layout (KT=64 / ASTR=72, warp-private A for gh) ----
#define NSTG   3
#define KTP    64
#define ASTRP  72
#define NKTP   (HDIM/KTP)                  // 16
#define APAIR  (16*ASTRP)                  // 1152 f16 per warp stage
#define APBLK  (NSTG*APAIR)                // 3456 f16 per warp
#define W_OFF  (8*APBLK)                   // 27648 f16
#define W_CH   (TN_S*ASTRP)                // 3456 f16 per k-chunk
#define BIAS_OFF (W_OFF + NKTP*W_CH)       // 82944 f16
#define SCGI_OFF (BIAS_OFF*2 + 256)        // bytes: after 64-float bias table
#define SC_PAIR  (16*49)                   // 784 floats per warp per buffer
#define SGI_BUF  (8*SC_PAIR)               // 6272 floats per parity buffer
#define SMEM_P   (SCGI_OFF + 2*SGI_BUF*4)  // 165888+256+50176 = 216320 B

// ---------------- device scratch ----------------
__device__ f16   g_W[(size_t)2*N3*KDIM];           // Whh at [dir][n][IDIM + k]
__device__ uint4 g_wfrag[(size_t)2*NBLK_S*6144];   // Wih in MMA B-fragment order
__device__ uint4 g_xfrag[(size_t)S_LEN*8*2048];    // x in MMA A-fragment order
__device__ float g_bias[2][4][HDIM];               // br, bz, b_in, b_hn
__device__ f16   g_hf[2*2*BATCH*HDIM];             // [parity][dir][b][j]
__device__ unsigned g_bar2[2];                     // per-dir barrier counters

// ---------------- helpers ----------------
__device__ __forceinline__ void cp16(f16* dst, const f16* src) {
    unsigned d = (unsigned)__cvta_generic_to_shared(dst);
    asm volatile("cp.async.cg.shared.global [%0], [%1], 16;\n" :: "r"(d), "l"(src));
}
__device__ __forceinline__ uint32_t smaddr(const void* p) {
    return (uint32_t)__cvta_generic_to_shared(p);
}
__device__ __forceinline__ void ldsm_x4(uint32_t r[4], uint32_t a) {
    asm volatile("ldmatrix.sync.aligned.m8n8.x4.shared.b16 {%0,%1,%2,%3},[%4];"
                 : "=r"(r[0]), "=r"(r[1]), "=r"(r[2]), "=r"(r[3]) : "r"(a));
}
__device__ __forceinline__ void mma16816(float c[4], const uint32_t a[4],
                                         uint32_t b0, uint32_t b1) {
    asm volatile(
        "mma.sync.aligned.m16n8k16.row.col.f32.f16.f16.f32 "
        "{%0,%1,%2,%3},{%4,%5,%6,%7},{%8,%9},{%0,%1,%2,%3};"
        : "+f"(c[0]), "+f"(c[1]), "+f"(c[2]), "+f"(c[3])
        : "r"(a[0]), "r"(a[1]), "r"(a[2]), "r"(a[3]), "r"(b0), "r"(b1));
}
__device__ __forceinline__ float fsig(float x) {
    return __fdividef(1.f, 1.f + __expf(-x));
}
__device__ __forceinline__ float ftanh(float x) {
    return 1.f - __fdividef(2.f, __expf(2.f * x) + 1.f);
}

#define CP_COMMIT() asm volatile("cp.async.commit_group;")

// ---------------- prep kernels ----------------
__global__ void pack_whh_kernel(const float* __restrict__ Whh_f, const float* __restrict__ Whh_b) {
    int idx = blockIdx.x * 256 + threadIdx.x;   // over 2*N3*HDIM
    int k   = idx & 1023;
    int n   = (idx >> 10) % N3;
    int dir = idx / (N3 * 1024);
    int j = n / 3, g = n % 3;
    const float* W = dir ? Whh_b : Whh_f;
    g_W[((size_t)dir * N3 + n) * KDIM + IDIM + k] =
        __float2half_rn(W[(g * HDIM + j) * HDIM + k]);
}

// Wih -> B-fragment layout: uint4 per (dir,nblk,kt,g2,lane), word i = b4[i]
__global__ void pack_wfrag_kernel(const float* __restrict__ Wih_f, const float* __restrict__ Wih_b) {
    int idx = blockIdx.x * 256 + threadIdx.x;   // over 3145728 u32
    int word = idx & 3;
    int lane = (idx >> 2) & 31;
    int v    = idx >> 7;
    int g2   = v % 12;
    int kt   = (v / 12) % 16;
    int nblk = (v / 192) % 64;
    int dir  = v / 12288;
    int nt = g2 >> 1, call = g2 & 1;
    int n = nblk * 48 + nt * 8 + (lane >> 2);
    int k = kt * 64 + call * 32 + word * 8 + (lane & 3) * 2;
    int srow = (n % 3) * HDIM + n / 3;
    const float* W = dir ? Wih_b : Wih_f;
    __half2 h2 = __halves2half2(__float2half_rn(W[(size_t)srow * IDIM + k]),
                                __float2half_rn(W[(size_t)srow * IDIM + k + 1]));
    ((uint32_t*)g_wfrag)[idx] = *(uint32_t*)&h2;
}

// x -> A-fragment layout: uint4 per (tf,w,kt,sub,lane); words = (r,c),(r+8,c),(r,c+8),(r+8,c+8)
__global__ void pack_xfrag_kernel(const float* __restrict__ x) {
    int idx = blockIdx.x * 256 + threadIdx.x;   // over S_LEN*8*16*4*32*4 = 33554432 u32
    int word = idx & 3;
    int lane = (idx >> 2) & 31;
    int sub  = (idx >> 7) & 3;
    int kt   = (idx >> 9) & 15;
    int w    = (idx >> 13) & 7;
    int tf   = idx >> 16;
    int brow = w * 16 + (word & 1) * 8 + (lane >> 2);
    int k    = kt * 64 + sub * 16 + ((word >> 1) & 1) * 8 + (lane & 3) * 2;
    const float* xr = x + ((size_t)tf * BATCH + brow) * IDIM + k;
    __half2 h2 = __halves2half2(__float2half_rn(xr[0]), __float2half_rn(xr[1]));
    ((uint32_t*)g_xfrag)[idx] = *(uint32_t*)&h2;
}

__global__ void pack_bias_kernel(const float* __restrict__ bih_f, const float* __restrict__ bhh_f,
                                 const float* __restrict__ bih_b, const float* __restrict__ bhh_b) {
    int i = blockIdx.x * 256 + threadIdx.x;   // 0..2047
    int dir = i >> 10, j = i & 1023;
    const float* bih = dir ? bih_b : bih_f;
    const float* bhh = dir ? bhh_b : bhh_f;
    g_bias[dir][0][j] = bih[j] + bhh[j];
    g_bias[dir][1][j] = bih[HDIM + j] + bhh[HDIM + j];
    g_bias[dir][2][j] = bih[2 * HDIM + j];
    g_bias[dir][3][j] = bhh[2 * HDIM + j];
}

__global__ void init_h_kernel() {
    int i = blockIdx.x * 256 + threadIdx.x;   // 2*2*B*H
    g_hf[i] = __float2half_rn(0.f);
    if (i < 2) g_bar2[i] = 0u;
}

// warp-private gh compute over 32 K (fp32 accumulators, proven path)
template<int NT>
__device__ __forceinline__ void compute_warp(f16* pA, f16* pW, int lane, float acc[NT][4]) {
    const uint32_t aoff = smaddr(pA + (lane & 15) * ASTRP + (lane >> 4) * 8);
    const uint32_t boff = smaddr(pW + (lane & 7) * ASTRP + (lane >> 3) * 8);
    uint32_t a0[4], a1[4];
    ldsm_x4(a0, aoff);
    ldsm_x4(a1, aoff + 16 * 2);
#pragma unroll
    for (int nt = 0; nt < NT; ++nt) {
        uint32_t b4[4];
        ldsm_x4(b4, boff + nt * 8 * ASTRP * 2);
        mma16816(acc[nt], a0, b4[0], b4[1]);
        mma16816(acc[nt], a1, b4[2], b4[3]);
    }
}

// ---------------- persistent fused kernel ----------------
// grid: (NBLK_S=64, 2) = 128 CTAs, block 256 (8 independent warps).
// gh: Whh smem-resident, warp-private A staging (R15-proven).
// gi: pure LDG fragment streams; after each odd step, computes gi for the
// next TWO steps sharing each B-fragment load (halves L2 B traffic).
__global__ void __launch_bounds__(256) gru_persist(float* __restrict__ out) {
    extern __shared__ char smraw[];
    f16* sm  = (f16*)smraw;
    f16* wsm = sm + W_OFF;
    float* sbias = (float*)(smraw + BIAS_OFF * 2);   // [4][16]

    const int nblk = blockIdx.x, dir = blockIdx.y;
    const int t = threadIdx.x, w = t >> 5, lane = t & 31;
    const int grp = lane >> 2, tq = lane & 3;
    f16* awarp = sm + w * APBLK;
    float* sGiBase = (float*)(smraw + SCGI_OFF);
    float* sGi0 = sGiBase + w * SC_PAIR;             // parity-0 buffer (this warp)
    float* sGi1 = sGiBase + SGI_BUF + w * SC_PAIR;   // parity-1 buffer

    // ---- preload Whh tile: 16 chunks x 48 rows x 64 k ----
    for (int i = t; i < NKTP * TN_S * 8; i += 256) {
        int kt   = i / (TN_S * 8);
        int r    = i % (TN_S * 8);
        int nloc = r >> 3, kq = (r & 7) * 8;
        size_t off = ((size_t)(dir * N3 + nblk * TN_S + nloc)) * KDIM + IDIM + kt * KTP + kq;
        cp16(wsm + kt * W_CH + nloc * ASTRP + kq, g_W + off);
    }
    if (t < 64) sbias[t] = g_bias[dir][t >> 4][nblk * 16 + (t & 15)];
    CP_COMMIT();
    asm volatile("cp.async.wait_group 0;");
    __syncthreads();

    // ---- per-thread persistent state: one b, 8 consecutive j ----
    const int brl    = lane >> 1;
    const int jh     = lane & 1;
    const int brow_g = w * 16 + brl;
    const int jb     = nblk * 16 + jh * 8;
    float hreg[8];
#pragma unroll
    for (int q = 0; q < 8; q++) hreg[q] = 0.f;

    const uint4* wfp = g_wfrag + (size_t)(dir * NBLK_S + nblk) * 6144 + lane;

    // ---- gi for two timesteps: pure LDG fragment streams, B loaded once ----
    auto gi_phase2 = [&](int tf1, int tf2, float* dst1, float* dst2) {
        const uint4* ap1 = g_xfrag + ((size_t)tf1 * 8 + w) * 2048 + lane;
        const uint4* ap2 = g_xfrag + ((size_t)tf2 * 8 + w) * 2048 + lane;
        float acc1[6][4], acc2[6][4];
#pragma unroll
        for (int i = 0; i < 6; i++)
#pragma unroll
            for (int q = 0; q < 4; q++) { acc1[i][q] = 0.f; acc2[i][q] = 0.f; }

#pragma unroll 1
        for (int kt = 0; kt < NKTP; ++kt) {
            uint4 bf[12];
#pragma unroll
            for (int g2 = 0; g2 < 12; g2++) bf[g2] = __ldg(wfp + (kt * 12 + g2) * 32);
            uint4 af1[4], af2[4];
#pragma unroll
            for (int s = 0; s < 4; s++) {
                af1[s] = __ldg(ap1 + (kt * 4 + s) * 32);
                af2[s] = __ldg(ap2 + (kt * 4 + s) * 32);
            }
#pragma unroll
            for (int nt = 0; nt < 6; ++nt) {
                mma16816(acc1[nt], (const uint32_t*)&af1[0], bf[nt * 2].x,     bf[nt * 2].y);
                mma16816(acc1[nt], (const uint32_t*)&af1[1], bf[nt * 2].z,     bf[nt * 2].w);
                mma16816(acc1[nt], (const uint32_t*)&af1[2], bf[nt * 2 + 1].x, bf[nt * 2 + 1].y);
                mma16816(acc1[nt], (const uint32_t*)&af1[3], bf[nt * 2 + 1].z, bf[nt * 2 + 1].w);
                mma16816(acc2[nt], (const uint32_t*)&af2[0], bf[nt * 2].x,     bf[nt * 2].y);
                mma16816(acc2[nt], (const uint32_t*)&af2[1], bf[nt * 2].z,     bf[nt * 2].w);
                mma16816(acc2[nt], (const uint32_t*)&af2[2], bf[nt * 2 + 1].x, bf[nt * 2 + 1].y);
                mma16816(acc2[nt], (const uint32_t*)&af2[3], bf[nt * 2 + 1].z, bf[nt * 2 + 1].w);
            }
        }
#pragma unroll
        for (int nt = 0; nt < 6; ++nt) {
            int col = nt * 8 + tq * 2;
            dst1[grp * 49 + col]           = acc1[nt][0];
            dst1[grp * 49 + col + 1]       = acc1[nt][1];
            dst1[(grp + 8) * 49 + col]     = acc1[nt][2];
            dst1[(grp + 8) * 49 + col + 1] = acc1[nt][3];
            dst2[grp * 49 + col]           = acc2[nt][0];
            dst2[grp * 49 + col + 1]       = acc2[nt][1];
            dst2[(grp + 8) * 49 + col]     = acc2[nt][2];
            dst2[(grp + 8) * 49 + col + 1] = acc2[nt][3];
        }
        __syncwarp();
    };

    auto tf_of = [&](int s) { return dir ? (S_LEN - 1 - s) : s; };

    // prologue: gi for steps 0 (buf0) and 1 (buf1)
    gi_phase2(tf_of(0), tf_of(1), sGi0, sGi1);

#pragma unroll 1
    for (int step = 0; step < S_LEN; ++step) {
        const int rpar = step & 1, wpar = rpar ^ 1;
        const int hbase = (rpar * 2 + dir) * BATCH * HDIM;

        auto copyA = [&](int kt, int buf) {
            f16* st = awarp + buf * APAIR;
#pragma unroll
            for (int i = 0; i < 4; i++) {
                int slot = lane + 32 * i;
                int rl = slot >> 3, kq = (slot & 7) * 8;
                int off = hbase + (w * 16 + rl) * HDIM + kt * KTP + kq;
                cp16(st + rl * ASTRP + kq, g_hf + off);
            }
        };

        float acc[6][4];
#pragma unroll
        for (int i = 0; i < 6; i++)
#pragma unroll
            for (int q = 0; q < 4; q++) acc[i][q] = 0.f;

        copyA(0, 0); CP_COMMIT();
        copyA(1, 1); CP_COMMIT();

#pragma unroll 1
        for (int kt = 0; kt < NKTP; ++kt) {
            if (kt < NKTP - 1) asm volatile("cp.async.wait_group 1;");
            else               asm volatile("cp.async.wait_group 0;");
            __syncwarp();
            if (kt + 2 < NKTP) { copyA(kt + 2, (kt + 2) % NSTG); CP_COMMIT(); }
            f16* pA = awarp + (kt % NSTG) * APAIR;
            f16* pW = wsm + kt * W_CH;
            compute_warp<6>(pA, pW, lane, acc);
            compute_warp<6>(pA + 32, pW + 32, lane, acc);
        }

        // ---- warp-local epilogue: frags -> warp scratch -> gates ----
        float* sC = (float*)awarp;                    // 16 x 49 floats
        {
#pragma unroll
            for (int nt = 0; nt < 6; ++nt) {
                int col = nt * 8 + tq * 2;
                sC[grp * 49 + col]           = acc[nt][0];
                sC[grp * 49 + col + 1]       = acc[nt][1];
                sC[(grp + 8) * 49 + col]     = acc[nt][2];
                sC[(grp + 8) * 49 + col + 1] = acc[nt][3];
            }
        }
        __syncwarp();

        const float* sGiCur = (rpar ? sGi1 : sGi0);
        const float* sRow   = sC + brl * 49 + jh * 24;
        const float* sRowGi = sGiCur + brl * 49 + jh * 24;
#pragma unroll
        for (int q = 0; q < 8; q++) {
            int jl = jh * 8 + q;
            float gr  = sRow[q * 3]     + sRowGi[q * 3]     + sbias[jl];
            float gz  = sRow[q * 3 + 1] + sRowGi[q * 3 + 1] + sbias[16 + jl];
            float gnh = sRow[q * 3 + 2] + sbias[48 + jl];
            float gni = sRowGi[q * 3 + 2] + sbias[32 + jl];
            float r = fsig(gr);
            float z = fsig(gz);
            float n = ftanh(gni + r * gnh);
            hreg[q] = (1.f - z) * n + z * hreg[q];
        }
        __syncwarp();

        // packed h store (8 consecutive f16 = 16 B)
        {
            __half2 p0 = __halves2half2(__float2half_rn(hreg[0]), __float2half_rn(hreg[1]));
            __half2 p1 = __halves2half2(__float2half_rn(hreg[2]), __float2half_rn(hreg[3]));
            __half2 p2 = __halves2half2(__float2half_rn(hreg[4]), __float2half_rn(hreg[5]));
            __half2 p3 = __halves2half2(__float2half_rn(hreg[6]), __float2half_rn(hreg[7]));
            uint4 v;
            v.x = *(const unsigned*)&p0;
            v.y = *(const unsigned*)&p1;
            v.z = *(const unsigned*)&p2;
            v.w = *(const unsigned*)&p3;
            *(uint4*)(g_hf + ((wpar * 2 + dir) * BATCH + brow_g) * HDIM + jb) = v;
        }

        __syncthreads();
        if (step < S_LEN - 1 && t == 0) {
            __threadfence();
            atomicAdd(&g_bar2[dir], 1u);
        }

        // out store (2x float4)
        {
            float* op = out + ((size_t)step * BATCH + brow_g) * (2 * HDIM) + dir * HDIM + jb;
            *(float4*)op       = make_float4(hreg[0], hreg[1], hreg[2], hreg[3]);
            *(float4*)(op + 4) = make_float4(hreg[4], hreg[5], hreg[6], hreg[7]);
        }

        if (step < S_LEN - 1) {
            // after odd steps: gi for the next TWO steps (both buffers free),
            // overlapping the barrier wait. B fragments loaded once for both.
            if (rpar == 1) {
                gi_phase2(tf_of(step + 1), tf_of(step + 2),
                          sGi0, sGi1);    // (step+1)&1==0 -> buf0, (step+2)&1==1 -> buf1
            }
            if (t == 0) {
                unsigned target = (unsigned)NBLK_S * (unsigned)(step + 1);
                while (*(volatile unsigned*)&g_bar2[dir] < target) __nanosleep(32);
                __threadfence();
            }
            __syncthreads();
        }
    }
}

// ---------------- launch ----------------
extern "C" void kernel_launch(void* const* d_in, const int* in_sizes, int n_in,
                              void* d_out, int out_size) {
    const float* x     = (const float*)d_in[0];
    const float* Wih_f = (const float*)d_in[1];
    const float* Whh_f = (const float*)d_in[2];
    const float* bih_f = (const float*)d_in[3];
    const float* bhh_f = (const float*)d_in[4];
    const float* Wih_b = (const float*)d_in[5];
    const float* Whh_b = (const float*)d_in[6];
    const float* bih_b = (const float*)d_in[7];
    const float* bhh_b = (const float*)d_in[8];
    float* out = (float*)d_out;

    cudaFuncSetAttribute(gru_persist, cudaFuncAttributeMaxDynamicSharedMemorySize, SMEM_P);

    pack_whh_kernel<<<2 * N3 * HDIM / 256, 256>>>(Whh_f, Whh_b);
    pack_wfrag_kernel<<<2 * NBLK_S * 6144 * 4 / 256, 256>>>(Wih_f, Wih_b);
    pack_xfrag_kernel<<<(int)((size_t)S_LEN * 8 * 2048 * 4 / 256), 256>>>(x);
    pack_bias_kernel<<<8, 256>>>(bih_f, bhh_f, bih_b, bhh_b);
    init_h_kernel<<<2 * 2 * BATCH * HDIM / 256, 256>>>();

    gru_persist<<<dim3(NBLK_S, 2), 256, SMEM_P>>>(out);
}